// round 4
// baseline (speedup 1.0000x reference)
#include <cuda_runtime.h>

#define HH 64
#define MM 256
#define VV 64
#define RFQ 16
#define NCHUNK 128
#define NB 4          // batches per block
#define NT 256        // threads per block
#define NGRID 128
#define TS 68         // padded row stride (floats): conflict-free for float4 row reads + column reads

// ---- precomputed tables in device globals (filled by setup kernel) ----
__device__ float VPg[12288];   // [3][64 vocab][64 j]
__device__ float RVTg[12288];  // [64 i][192 row]
__device__ float ATg[4096];    // [64 c][64 i]
__device__ float A0g[64];
__device__ float RV0g[192];

// smem offsets (floats)
#define OFF_RVT   0            // 12288
#define OFF_AT    12288        // 4096
#define OFF_A0    16384        // 64
#define OFF_RV0   16448        // 192
#define OFF_WALL  16640        // 192*68 = 13056 (all W_hh rows, padded)
#define OFF_TILE  29696        // 4 * 64*68 = 17408
#define OFF_HS    47104        // 4 * 2 * 64
#define OFF_QS    47616        // 4 * 64
#define OFF_SS    47872
#define OFF_ES    48128
#define OFF_RS    48384
#define OFF_TOK   48640        // 64 ints
#define SMEM_FLOATS 48704      // 194816 bytes

typedef unsigned long long ull;

__device__ __forceinline__ void gbar(int id) {
    asm volatile("bar.sync %0, 64;" :: "r"(id) : "memory");
}
__device__ __forceinline__ float sigmoidf_(float x) {
    float e = __expf(-x);
    return __fdividef(1.f, 1.f + e);
}
__device__ __forceinline__ float tanhf_(float x) {
    float e = __expf(2.f * x);
    return 1.f - __fdividef(2.f, e + 1.f);
}
__device__ __forceinline__ ull pk(float a, float b) {
    ull r; asm("mov.b64 %0, {%1,%2};" : "=l"(r) : "f"(a), "f"(b)); return r;
}
__device__ __forceinline__ void fma2(ull& d, ull a, ull b) {
    asm("fma.rn.f32x2 %0, %1, %2, %0;" : "+l"(d) : "l"(a), "l"(b));
}
__device__ __forceinline__ float2 upk(ull a) {
    float2 f; asm("mov.b64 {%0,%1}, %2;" : "=f"(f.x), "=f"(f.y) : "l"(a)); return f;
}

// ---- setup kernel: fold all token/attention algebra once ----
__global__ void setup_k(const float* __restrict__ embed_w, const float* __restrict__ w_ih,
                        const float* __restrict__ b_ih, const float* __restrict__ key_w,
                        const float* __restrict__ val_w, const float* __restrict__ val_b,
                        const float* __restrict__ query_w, const float* __restrict__ query_b)
{
    const int idx = blockIdx.x * 256 + threadIdx.x;
    if (idx < 12288) {
        // VP[g][v][jj] = emb[v] . W_ih_x[row] + b_ih[row],  row = g*64+jj
        const int g = idx >> 12, v = (idx >> 6) & 63, jj = idx & 63;
        const int row = g * 64 + jj;
        float acc = b_ih[row];
#pragma unroll 8
        for (int c = 0; c < 64; c++) acc = fmaf(embed_w[v * 64 + c], w_ih[row * 128 + c], acc);
        VPg[idx] = acc;
    } else if (idx < 24576) {
        // RVT[i][row] = sum_k W_ih_ret[row][k] * val_w[k][i]
        const int t = idx - 12288;
        const int i = t / 192, row = t % 192;
        float acc = 0.f;
#pragma unroll 8
        for (int k = 0; k < 64; k++) acc = fmaf(w_ih[row * 128 + 64 + k], val_w[k * 64 + i], acc);
        RVTg[i * 192 + row] = acc;
    } else if (idx < 28672) {
        // AT[c][i] = scale * sum_k key_w[k][i]*query_w[k][c]
        const int t = idx - 24576;
        const int c = t >> 6, i = t & 63;
        float acc = 0.f;
#pragma unroll 8
        for (int k = 0; k < 64; k++) acc = fmaf(key_w[k * 64 + i], query_w[k * 64 + c], acc);
        ATg[c * 64 + i] = acc * 0.125f;
    } else if (idx < 28736) {
        const int i = idx - 28672;
        float acc = 0.f;
#pragma unroll 8
        for (int k = 0; k < 64; k++) acc = fmaf(key_w[k * 64 + i], query_b[k], acc);
        A0g[i] = acc * 0.125f;
    } else if (idx < 28928) {
        const int row = idx - 28736;
        float acc = 0.f;
#pragma unroll 8
        for (int k = 0; k < 64; k++) acc = fmaf(w_ih[row * 128 + 64 + k], val_b[k], acc);
        RV0g[row] = acc;
    }
}

__global__ void __launch_bounds__(NT, 1) ffm_kernel(
    const int*   __restrict__ seq,
    const float* __restrict__ memory,
    const float* __restrict__ w_hh,
    const float* __restrict__ b_hh,
    const float* __restrict__ head_w,
    const float* __restrict__ head_b,
    float* __restrict__ out)
{
    extern __shared__ float sm[];
    float* RVT = sm + OFF_RVT;
    float* AT  = sm + OFF_AT;
    float* A0  = sm + OFF_A0;
    float* RV0 = sm + OFF_RV0;

    const int tid = threadIdx.x;
    const int j   = tid & 63;
    const int bl  = tid >> 6;
    const int bg  = blockIdx.x * NB + bl;

    // ---- copy tables + weights into shared ----
    for (int e = tid; e < 12288; e += NT) {
        RVT[e] = RVTg[e];
        const int row = e >> 6, i = e & 63;
        sm[OFF_WALL + row * TS + i] = w_hh[e];
    }
    for (int e = tid; e < 4096; e += NT) AT[e] = ATg[e];
    if (tid < 64)  A0[tid]  = A0g[tid];
    if (tid < 192) RV0[tid] = RV0g[tid];

    float* TILEb = sm + OFF_TILE + bl * (64 * TS);
    float* HSb   = sm + OFF_HS   + bl * 128;
    float* QSb   = sm + OFF_QS   + bl * 64;
    float* SSb   = sm + OFF_SS   + bl * 64;
    float* ESb   = sm + OFF_ES   + bl * 64;
    float* RSb   = sm + OFF_RS   + bl * 64;
    int*   TOKb  = (int*)(sm + OFF_TOK) + bl * 16;

    HSb[j] = 0.f; HSb[64 + j] = 0.f;
    float h = 0.f;
    const float* memb = memory + (size_t)bg * (MM * HH);
    const int*   seqb = seq + (size_t)bg * 2048;
    const int barid = bl + 1;
    const ull BHR2 = pk(b_hh[j], 0.f);
    const ull BHZ2 = pk(b_hh[64 + j], 0.f);
    const ull BHN2 = pk(b_hh[128 + j], 0.f);
    __syncthreads();

#pragma unroll 1
    for (int ch = 0; ch < NCHUNK; ch++) {
        // tokens + query (h lives in HS buffer 0 at chunk boundaries)
        if (j < 16) TOKb[j] = seqb[ch * RFQ + j];
        float qt = A0[j];
#pragma unroll 8
        for (int c = 0; c < 64; c++) qt = fmaf(AT[c * 64 + j], HSb[c], qt);
        QSb[j] = qt;

        // register-prefetch tile 0 (global loads: no smem hazard)
        float4 pf[16];
        const float4* mt4 = (const float4*)memb;
#pragma unroll
        for (int it = 0; it < 16; it++) pf[it] = mt4[it * 64 + j];
        gbar(barid);

        // ---- single pass over memory: online softmax + weighted accumulation ----
        float Mx = -1e30f, D = 0.f, macc = 0.f;
#pragma unroll 1
        for (int t4 = 0; t4 < 4; t4++) {
            // store prefetched tile
#pragma unroll
            for (int it = 0; it < 16; it++) {
                const int e4 = it * 64 + j;
                const int r = e4 >> 4, c4 = e4 & 15;
                *(float4*)(TILEb + r * TS + c4 * 4) = pf[it];
            }
            // prefetch next tile while this one is consumed
            if (t4 < 3) {
                const float4* nt4 = mt4 + (t4 + 1) * 1024;
#pragma unroll
                for (int it = 0; it < 16; it++) pf[it] = nt4[it * 64 + j];
            }
            gbar(barid);
            // score for row m=j
            float s = 0.f;
            {
                const float4* q4 = (const float4*)QSb;
                const float4* row4 = (const float4*)(TILEb + j * TS);
#pragma unroll
                for (int i4 = 0; i4 < 16; i4++) {
                    const float4 qv = q4[i4], rv = row4[i4];
                    s = fmaf(qv.x, rv.x, s); s = fmaf(qv.y, rv.y, s);
                    s = fmaf(qv.z, rv.z, s); s = fmaf(qv.w, rv.w, s);
                }
            }
            SSb[j] = s;
            gbar(barid);
            float tm = -1e30f;
#pragma unroll 8
            for (int m = 0; m < 64; m++) tm = fmaxf(tm, SSb[m]);
            const float nM = fmaxf(Mx, tm);
            const float alpha = __expf(Mx - nM);
            ESb[j] = __expf(s - nM);
            gbar(barid);
            macc *= alpha; D *= alpha;
#pragma unroll 8
            for (int m = 0; m < 64; m++) {
                const float em = ESb[m];
                macc = fmaf(em, TILEb[m * TS + j], macc);
                D += em;
            }
            Mx = nM;
            gbar(barid);
        }
        RSb[j] = macc / D;
        gbar(barid);

        // r_proj rows {j, 64+j, 128+j}
        float rp_r = RV0[j], rp_z = RV0[64 + j], rp_n = RV0[128 + j];
#pragma unroll 8
        for (int i = 0; i < 64; i++) {
            const float rv = RSb[i];
            rp_r = fmaf(RVT[i * 192 + j], rv, rp_r);
            rp_z = fmaf(RVT[i * 192 + 64 + j], rv, rp_z);
            rp_n = fmaf(RVT[i * 192 + 128 + j], rv, rp_n);
        }

        // ---- reload all W_hh weights into registers (packed f32x2), once per chunk ----
        ull wr2[32], wz2[32], wn2[32];
        {
            const float4* wrp = (const float4*)(sm + OFF_WALL + j * TS);
            const float4* wzp = (const float4*)(sm + OFF_WALL + (64 + j) * TS);
            const float4* wnp = (const float4*)(sm + OFF_WALL + (128 + j) * TS);
#pragma unroll
            for (int i4 = 0; i4 < 16; i4++) {
                float4 a = wrp[i4]; wr2[2 * i4] = pk(a.x, a.y); wr2[2 * i4 + 1] = pk(a.z, a.w);
                float4 b = wzp[i4]; wz2[2 * i4] = pk(b.x, b.y); wz2[2 * i4 + 1] = pk(b.z, b.w);
                float4 c = wnp[i4]; wn2[2 * i4] = pk(c.x, c.y); wn2[2 * i4 + 1] = pk(c.z, c.w);
            }
        }

        // ---- 16 GRU steps (FFMA2 dot products) ----
        int curl = 0;
#pragma unroll 1
        for (int st = 0; st < RFQ; st++) {
            const int tok = TOKb[st];
            const float gxr = VPg[tok * 64 + j] + rp_r;
            const float gxz = VPg[4096 + tok * 64 + j] + rp_z;
            const float gxn = VPg[8192 + tok * 64 + j] + rp_n;
            const float4* h4 = (const float4*)(HSb + curl * 64);
            ull ar = BHR2, az = BHZ2, an = BHN2;
#pragma unroll
            for (int i4 = 0; i4 < 16; i4++) {
                const float4 hv = h4[i4];
                const ull h01 = pk(hv.x, hv.y), h23 = pk(hv.z, hv.w);
                fma2(ar, wr2[2 * i4], h01); fma2(az, wz2[2 * i4], h01); fma2(an, wn2[2 * i4], h01);
                fma2(ar, wr2[2 * i4 + 1], h23); fma2(az, wz2[2 * i4 + 1], h23); fma2(an, wn2[2 * i4 + 1], h23);
            }
            const float2 fr = upk(ar), fz = upk(az), fn = upk(an);
            const float r = sigmoidf_(gxr + fr.x + fr.y);
            const float z = sigmoidf_(gxz + fz.x + fz.y);
            const float n = tanhf_(gxn + r * (fn.x + fn.y));
            const float hn = fmaf(z, h - n, n);
            HSb[(curl ^ 1) * 64 + j] = hn;
            h = hn;
            gbar(barid);
            curl ^= 1;
        }
    }

    // ---- head (h is in HS buffer 0) ----
    float o = head_b[j];
#pragma unroll 8
    for (int i = 0; i < 64; i++) o = fmaf(head_w[j * 64 + i], HSb[i], o);
    out[(size_t)bg * VV + j] = o;
}

extern "C" void kernel_launch(void* const* d_in, const int* in_sizes, int n_in,
                              void* d_out, int out_size) {
    const int*   seq      = (const int*)  d_in[0];
    const float* memory   = (const float*)d_in[1];
    const float* embed_w  = (const float*)d_in[2];
    const float* w_ih     = (const float*)d_in[3];
    const float* w_hh     = (const float*)d_in[4];
    const float* b_ih     = (const float*)d_in[5];
    const float* b_hh     = (const float*)d_in[6];
    const float* key_w    = (const float*)d_in[7];
    const float* key_b    = (const float*)d_in[8];   // cancels in softmax (constant over m)
    const float* val_w    = (const float*)d_in[9];
    const float* val_b    = (const float*)d_in[10];
    const float* query_w  = (const float*)d_in[11];
    const float* query_b  = (const float*)d_in[12];
    const float* head_w   = (const float*)d_in[13];
    const float* head_b   = (const float*)d_in[14];
    (void)key_b;

    setup_k<<<113, 256>>>(embed_w, w_ih, b_ih, key_w, val_w, val_b, query_w, query_b);

    const size_t shmem = (size_t)SMEM_FLOATS * sizeof(float);
    cudaFuncSetAttribute(ffm_kernel, cudaFuncAttributeMaxDynamicSharedMemorySize, (int)shmem);
    ffm_kernel<<<NGRID, NT, shmem>>>(seq, memory, w_hh, b_hh, head_w, head_b, (float*)d_out);
}

// round 5
// speedup vs baseline: 1.0021x; 1.0021x over previous
#include <cuda_runtime.h>

#define HH 64
#define MM 256
#define VV 64
#define RFQ 16
#define NCHUNK 128
#define NB 4          // batches per block
#define NT 256        // threads per block
#define NGRID 128
#define TS 68         // padded row stride (floats): conflict-free for float4 row reads + column reads

// ---- precomputed tables in device globals (filled by setup kernel) ----
__device__ float VPg[12288];   // [3][64 vocab][64 j]
__device__ float RVTg[12288];  // [64 i][192 row]
__device__ float ATg[4096];    // [64 c][64 i]
__device__ float A0g[64];
__device__ float RV0g[192];

// smem offsets (floats)
#define OFF_RVT   0            // 12288
#define OFF_AT    12288        // 4096
#define OFF_A0    16384        // 64
#define OFF_RV0   16448        // 192
#define OFF_WALL  16640        // 192*68 = 13056 (all W_hh rows, padded)
#define OFF_TILE  29696        // 4 * 64*68 = 17408
#define OFF_HS    47104        // 4 * 2 * 64
#define OFF_QS    47616        // 4 * 64
#define OFF_SS    47872
#define OFF_ES    48128
#define OFF_RS    48384
#define OFF_TOK   48640        // 64 ints
#define SMEM_FLOATS 48704      // 194816 bytes

typedef unsigned long long ull;

__device__ __forceinline__ void gbar(int id) {
    asm volatile("bar.sync %0, 64;" :: "r"(id) : "memory");
}
__device__ __forceinline__ float sigmoidf_(float x) {
    float e = __expf(-x);
    return __fdividef(1.f, 1.f + e);
}
__device__ __forceinline__ float tanhf_(float x) {
    float e = __expf(2.f * x);
    return 1.f - __fdividef(2.f, e + 1.f);
}
__device__ __forceinline__ ull pk(float a, float b) {
    ull r; asm("mov.b64 %0, {%1,%2};" : "=l"(r) : "f"(a), "f"(b)); return r;
}
__device__ __forceinline__ void fma2(ull& d, ull a, ull b) {
    asm("fma.rn.f32x2 %0, %1, %2, %0;" : "+l"(d) : "l"(a), "l"(b));
}
__device__ __forceinline__ float2 upk(ull a) {
    float2 f; asm("mov.b64 {%0,%1}, %2;" : "=f"(f.x), "=f"(f.y) : "l"(a)); return f;
}

// ---- setup kernel: fold all token/attention algebra once ----
__global__ void setup_k(const float* __restrict__ embed_w, const float* __restrict__ w_ih,
                        const float* __restrict__ b_ih, const float* __restrict__ key_w,
                        const float* __restrict__ val_w, const float* __restrict__ val_b,
                        const float* __restrict__ query_w, const float* __restrict__ query_b)
{
    const int idx = blockIdx.x * 256 + threadIdx.x;
    if (idx < 12288) {
        // VP[g][v][jj] = emb[v] . W_ih_x[row] + b_ih[row],  row = g*64+jj
        const int g = idx >> 12, v = (idx >> 6) & 63, jj = idx & 63;
        const int row = g * 64 + jj;
        float acc = b_ih[row];
#pragma unroll 8
        for (int c = 0; c < 64; c++) acc = fmaf(embed_w[v * 64 + c], w_ih[row * 128 + c], acc);
        VPg[idx] = acc;
    } else if (idx < 24576) {
        // RVT[i][row] = sum_k W_ih_ret[row][k] * val_w[k][i]
        const int t = idx - 12288;
        const int i = t / 192, row = t % 192;
        float acc = 0.f;
#pragma unroll 8
        for (int k = 0; k < 64; k++) acc = fmaf(w_ih[row * 128 + 64 + k], val_w[k * 64 + i], acc);
        RVTg[i * 192 + row] = acc;
    } else if (idx < 28672) {
        // AT[c][i] = scale * sum_k key_w[k][i]*query_w[k][c]
        const int t = idx - 24576;
        const int c = t >> 6, i = t & 63;
        float acc = 0.f;
#pragma unroll 8
        for (int k = 0; k < 64; k++) acc = fmaf(key_w[k * 64 + i], query_w[k * 64 + c], acc);
        ATg[c * 64 + i] = acc * 0.125f;
    } else if (idx < 28736) {
        const int i = idx - 28672;
        float acc = 0.f;
#pragma unroll 8
        for (int k = 0; k < 64; k++) acc = fmaf(key_w[k * 64 + i], query_b[k], acc);
        A0g[i] = acc * 0.125f;
    } else if (idx < 28928) {
        const int row = idx - 28736;
        float acc = 0.f;
#pragma unroll 8
        for (int k = 0; k < 64; k++) acc = fmaf(w_ih[row * 128 + 64 + k], val_b[k], acc);
        RV0g[row] = acc;
    }
}

__global__ void __launch_bounds__(NT, 1) ffm_kernel(
    const int*   __restrict__ seq,
    const float* __restrict__ memory,
    const float* __restrict__ w_hh,
    const float* __restrict__ b_hh,
    const float* __restrict__ head_w,
    const float* __restrict__ head_b,
    float* __restrict__ out)
{
    extern __shared__ float sm[];
    float* RVT = sm + OFF_RVT;
    float* AT  = sm + OFF_AT;
    float* A0  = sm + OFF_A0;
    float* RV0 = sm + OFF_RV0;

    const int tid = threadIdx.x;
    const int j   = tid & 63;
    const int bl  = tid >> 6;
    const int bg  = blockIdx.x * NB + bl;

    // ---- copy tables + weights into shared ----
    for (int e = tid; e < 12288; e += NT) {
        RVT[e] = RVTg[e];
        const int row = e >> 6, i = e & 63;
        sm[OFF_WALL + row * TS + i] = w_hh[e];
    }
    for (int e = tid; e < 4096; e += NT) AT[e] = ATg[e];
    if (tid < 64)  A0[tid]  = A0g[tid];
    if (tid < 192) RV0[tid] = RV0g[tid];

    float* TILEb = sm + OFF_TILE + bl * (64 * TS);
    float* HSb   = sm + OFF_HS   + bl * 128;
    float* QSb   = sm + OFF_QS   + bl * 64;
    float* SSb   = sm + OFF_SS   + bl * 64;
    float* ESb   = sm + OFF_ES   + bl * 64;
    float* RSb   = sm + OFF_RS   + bl * 64;
    int*   TOKb  = (int*)(sm + OFF_TOK) + bl * 16;

    HSb[j] = 0.f; HSb[64 + j] = 0.f;
    float h = 0.f;
    const float* memb = memory + (size_t)bg * (MM * HH);
    const int*   seqb = seq + (size_t)bg * 2048;
    const int barid = bl + 1;
    const ull BHR2 = pk(b_hh[j], 0.f);
    const ull BHZ2 = pk(b_hh[64 + j], 0.f);
    const ull BHN2 = pk(b_hh[128 + j], 0.f);
    __syncthreads();

#pragma unroll 1
    for (int ch = 0; ch < NCHUNK; ch++) {
        // tokens + query (h lives in HS buffer 0 at chunk boundaries)
        if (j < 16) TOKb[j] = seqb[ch * RFQ + j];
        float qt = A0[j];
#pragma unroll 8
        for (int c = 0; c < 64; c++) qt = fmaf(AT[c * 64 + j], HSb[c], qt);
        QSb[j] = qt;

        // register-prefetch tile 0 (global loads: no smem hazard)
        float4 pf[16];
        const float4* mt4 = (const float4*)memb;
#pragma unroll
        for (int it = 0; it < 16; it++) pf[it] = mt4[it * 64 + j];
        gbar(barid);

        // ---- single pass over memory: online softmax + weighted accumulation ----
        float Mx = -1e30f, D = 0.f, macc = 0.f;
#pragma unroll 1
        for (int t4 = 0; t4 < 4; t4++) {
            // store prefetched tile
#pragma unroll
            for (int it = 0; it < 16; it++) {
                const int e4 = it * 64 + j;
                const int r = e4 >> 4, c4 = e4 & 15;
                *(float4*)(TILEb + r * TS + c4 * 4) = pf[it];
            }
            // prefetch next tile while this one is consumed
            if (t4 < 3) {
                const float4* nt4 = mt4 + (t4 + 1) * 1024;
#pragma unroll
                for (int it = 0; it < 16; it++) pf[it] = nt4[it * 64 + j];
            }
            gbar(barid);
            // score for row m=j
            float s = 0.f;
            {
                const float4* q4 = (const float4*)QSb;
                const float4* row4 = (const float4*)(TILEb + j * TS);
#pragma unroll
                for (int i4 = 0; i4 < 16; i4++) {
                    const float4 qv = q4[i4], rv = row4[i4];
                    s = fmaf(qv.x, rv.x, s); s = fmaf(qv.y, rv.y, s);
                    s = fmaf(qv.z, rv.z, s); s = fmaf(qv.w, rv.w, s);
                }
            }
            SSb[j] = s;
            gbar(barid);
            float tm = -1e30f;
#pragma unroll 8
            for (int m = 0; m < 64; m++) tm = fmaxf(tm, SSb[m]);
            const float nM = fmaxf(Mx, tm);
            const float alpha = __expf(Mx - nM);
            ESb[j] = __expf(s - nM);
            gbar(barid);
            macc *= alpha; D *= alpha;
#pragma unroll 8
            for (int m = 0; m < 64; m++) {
                const float em = ESb[m];
                macc = fmaf(em, TILEb[m * TS + j], macc);
                D += em;
            }
            Mx = nM;
            gbar(barid);
        }
        RSb[j] = macc / D;
        gbar(barid);

        // r_proj rows {j, 64+j, 128+j}
        float rp_r = RV0[j], rp_z = RV0[64 + j], rp_n = RV0[128 + j];
#pragma unroll 8
        for (int i = 0; i < 64; i++) {
            const float rv = RSb[i];
            rp_r = fmaf(RVT[i * 192 + j], rv, rp_r);
            rp_z = fmaf(RVT[i * 192 + 64 + j], rv, rp_z);
            rp_n = fmaf(RVT[i * 192 + 128 + j], rv, rp_n);
        }

        // ---- reload all W_hh weights into registers (packed f32x2), once per chunk ----
        ull wr2[32], wz2[32], wn2[32];
        {
            const float4* wrp = (const float4*)(sm + OFF_WALL + j * TS);
            const float4* wzp = (const float4*)(sm + OFF_WALL + (64 + j) * TS);
            const float4* wnp = (const float4*)(sm + OFF_WALL + (128 + j) * TS);
#pragma unroll
            for (int i4 = 0; i4 < 16; i4++) {
                float4 a = wrp[i4]; wr2[2 * i4] = pk(a.x, a.y); wr2[2 * i4 + 1] = pk(a.z, a.w);
                float4 b = wzp[i4]; wz2[2 * i4] = pk(b.x, b.y); wz2[2 * i4 + 1] = pk(b.z, b.w);
                float4 c = wnp[i4]; wn2[2 * i4] = pk(c.x, c.y); wn2[2 * i4 + 1] = pk(c.z, c.w);
            }
        }

        // ---- 16 GRU steps (FFMA2 dot products) ----
        int curl = 0;
#pragma unroll 1
        for (int st = 0; st < RFQ; st++) {
            const int tok = TOKb[st];
            const float gxr = VPg[tok * 64 + j] + rp_r;
            const float gxz = VPg[4096 + tok * 64 + j] + rp_z;
            const float gxn = VPg[8192 + tok * 64 + j] + rp_n;
            const float4* h4 = (const float4*)(HSb + curl * 64);
            ull ar = BHR2, az = BHZ2, an = BHN2;
#pragma unroll
            for (int i4 = 0; i4 < 16; i4++) {
                const float4 hv = h4[i4];
                const ull h01 = pk(hv.x, hv.y), h23 = pk(hv.z, hv.w);
                fma2(ar, wr2[2 * i4], h01); fma2(az, wz2[2 * i4], h01); fma2(an, wn2[2 * i4], h01);
                fma2(ar, wr2[2 * i4 + 1], h23); fma2(az, wz2[2 * i4 + 1], h23); fma2(an, wn2[2 * i4 + 1], h23);
            }
            const float2 fr = upk(ar), fz = upk(az), fn = upk(an);
            const float r = sigmoidf_(gxr + fr.x + fr.y);
            const float z = sigmoidf_(gxz + fz.x + fz.y);
            const float n = tanhf_(gxn + r * (fn.x + fn.y));
            const float hn = fmaf(z, h - n, n);
            HSb[(curl ^ 1) * 64 + j] = hn;
            h = hn;
            gbar(barid);
            curl ^= 1;
        }
    }

    // ---- head (h is in HS buffer 0) ----
    float o = head_b[j];
#pragma unroll 8
    for (int i = 0; i < 64; i++) o = fmaf(head_w[j * 64 + i], HSb[i], o);
    out[(size_t)bg * VV + j] = o;
}

extern "C" void kernel_launch(void* const* d_in, const int* in_sizes, int n_in,
                              void* d_out, int out_size) {
    const int*   seq      = (const int*)  d_in[0];
    const float* memory   = (const float*)d_in[1];
    const float* embed_w  = (const float*)d_in[2];
    const float* w_ih     = (const float*)d_in[3];
    const float* w_hh     = (const float*)d_in[4];
    const float* b_ih     = (const float*)d_in[5];
    const float* b_hh     = (const float*)d_in[6];
    const float* key_w    = (const float*)d_in[7];
    const float* key_b    = (const float*)d_in[8];   // cancels in softmax (constant over m)
    const float* val_w    = (const float*)d_in[9];
    const float* val_b    = (const float*)d_in[10];
    const float* query_w  = (const float*)d_in[11];
    const float* query_b  = (const float*)d_in[12];
    const float* head_w   = (const float*)d_in[13];
    const float* head_b   = (const float*)d_in[14];
    (void)key_b;

    setup_k<<<113, 256>>>(embed_w, w_ih, b_ih, key_w, val_w, val_b, query_w, query_b);

    const size_t shmem = (size_t)SMEM_FLOATS * sizeof(float);
    cudaFuncSetAttribute(ffm_kernel, cudaFuncAttributeMaxDynamicSharedMemorySize, (int)shmem);
    ffm_kernel<<<NGRID, NT, shmem>>>(seq, memory, w_hh, b_hh, head_w, head_b, (float*)d_out);
}